// round 2
// baseline (speedup 1.0000x reference)
#include <cuda_runtime.h>
#include <cstdint>

#define N_GAUSS 4096
#define NPAIR   2048
#define NSLICE  4
#define EPSF    1e-6f
// -0.5 * log2(e)
#define NHL2E  -0.72134752044448170367996234050095f

// Scratch (allocation-free rule: __device__ globals)
__device__ float g_maxdist;
// pair-interleaved table: per slice, per gaussian-pair kp, 16 floats:
// [NA(a,b), NB2(a,b), ND(a,b), NMX(a,b), NMY(a,b), OP(a,b), OFT(a,b), pad(a,b)]
// where NA = -0.5*log2(e)*A, NB2 = -0.5*log2(e)*2B, ND = -0.5*log2(e)*D,
// NMX = -mu_x(slice), NMY = -mu_y(slice), OP = mask*op, OFT = mask*op*ft.
__device__ __align__(16) float g_table[NSLICE * NPAIR * 16];

// ---------------------------------------------------------------------------
// packed f32x2 helpers
// ---------------------------------------------------------------------------
__device__ __forceinline__ uint64_t pk2(float lo, float hi) {
    uint64_t r;
    asm("mov.b64 %0, {%1,%2};" : "=l"(r) : "f"(lo), "f"(hi));
    return r;
}
__device__ __forceinline__ void upk2(uint64_t v, float& lo, float& hi) {
    asm("mov.b64 {%0,%1}, %2;" : "=f"(lo), "=f"(hi) : "l"(v));
}
__device__ __forceinline__ uint64_t fma2(uint64_t a, uint64_t b, uint64_t c) {
    uint64_t d;
    asm("fma.rn.f32x2 %0, %1, %2, %3;" : "=l"(d) : "l"(a), "l"(b), "l"(c));
    return d;
}
__device__ __forceinline__ uint64_t mul2(uint64_t a, uint64_t b) {
    uint64_t d;
    asm("mul.rn.f32x2 %0, %1, %2;" : "=l"(d) : "l"(a), "l"(b));
    return d;
}
__device__ __forceinline__ uint64_t add2(uint64_t a, uint64_t b) {
    uint64_t d;
    asm("add.rn.f32x2 %0, %1, %2;" : "=l"(d) : "l"(a), "l"(b));
    return d;
}
__device__ __forceinline__ float ex2a(float x) {
    float r;
    asm("ex2.approx.f32 %0, %1;" : "=f"(r) : "f"(x));
    return r;
}

// ---------------------------------------------------------------------------
// Kernel 1: max over scales[:,2] -> g_maxdist = 3*max
// ---------------------------------------------------------------------------
__global__ void k_maxscale(const float* __restrict__ scales) {
    __shared__ float sm[256];
    float m = -1e30f;
    for (int k = threadIdx.x; k < N_GAUSS; k += 256)
        m = fmaxf(m, scales[k * 3 + 2]);
    sm[threadIdx.x] = m;
    __syncthreads();
    for (int s = 128; s > 0; s >>= 1) {
        if (threadIdx.x < s) sm[threadIdx.x] = fmaxf(sm[threadIdx.x], sm[threadIdx.x + s]);
        __syncthreads();
    }
    if (threadIdx.x == 0) g_maxdist = 3.0f * sm[0];
}

// ---------------------------------------------------------------------------
// Kernel 2: per-gaussian precompute -> coefficient table (pair-interleaved)
// ---------------------------------------------------------------------------
__global__ void k_precompute(const float* __restrict__ means,
                             const float* __restrict__ scales,
                             const float* __restrict__ rot,
                             const float* __restrict__ opac,
                             const float* __restrict__ feat) {
    int k = blockIdx.x * blockDim.x + threadIdx.x;
    if (k >= N_GAUSS) return;

    float qw = rot[k * 4 + 0], qx = rot[k * 4 + 1], qy = rot[k * 4 + 2], qz = rot[k * 4 + 3];
    float nrm = sqrtf(qw * qw + qx * qx + qy * qy + qz * qz);
    float inq = 1.0f / nrm;
    float w = qw * inq, x = qx * inq, y = qy * inq, z = qz * inq;

    float r00 = 1.f - 2.f * (y * y + z * z);
    float r01 = 2.f * (x * y - w * z);
    float r02 = 2.f * (x * z + w * y);
    float r10 = 2.f * (x * y + w * z);
    float r11 = 1.f - 2.f * (x * x + z * z);
    float r12 = 2.f * (y * z - w * x);
    float r20 = 2.f * (x * z - w * y);
    float r21 = 2.f * (y * z + w * x);
    float r22 = 1.f - 2.f * (x * x + y * y);

    float sx = scales[k * 3 + 0], sy = scales[k * 3 + 1], sz = scales[k * 3 + 2];
    // M = R * diag(s)
    float m00 = r00 * sx, m01 = r01 * sy, m02 = r02 * sz;
    float m10 = r10 * sx, m11 = r11 * sy, m12 = r12 * sz;
    float m20 = r20 * sx, m21 = r21 * sy, m22 = r22 * sz;

    // cov = M M^T (needed entries)
    float c00 = m00 * m00 + m01 * m01 + m02 * m02;
    float c01 = m00 * m10 + m01 * m11 + m02 * m12;
    float c11 = m10 * m10 + m11 * m11 + m12 * m12;
    float c02 = m00 * m20 + m01 * m21 + m02 * m22;
    float c12 = m10 * m20 + m11 * m21 + m12 * m22;
    float c22 = m20 * m20 + m21 * m21 + m22 * m22;

    float szz = c22 + EPSF;
    float rx = c02 / szz;   // mu2d shift coefficients
    float ry = c12 / szz;

    float s00 = c00 - c02 * c02 / szz + EPSF;
    float s01 = c01 - c02 * c12 / szz;
    float s11 = c11 - c12 * c12 / szz + EPSF;
    float det = s00 * s11 - s01 * s01;
    float A  = s11 / det;
    float Bc = -s01 / det;
    float D  = s00 / det;

    float NA  = NHL2E * A;
    float NB2 = NHL2E * 2.0f * Bc;
    float ND  = NHL2E * D;

    float mx0 = means[k * 3 + 0], my0 = means[k * 3 + 1], mz = means[k * 3 + 2];
    float op = opac[k];
    float ft = feat[k];
    float md = g_maxdist;

    int kp = k >> 1;
    int h  = k & 1;

#pragma unroll
    for (int s = 0; s < NSLICE; s++) {
        float zs = -0.15f + 0.1f * (float)s;   // linspace(-0.15, 0.15, 4)
        float zoff = zs - mz;
        float mx = mx0 + rx * zoff;
        float my = my0 + ry * zoff;
        float mask = (fabsf(mz - zs) < md) ? 1.0f : 0.0f;

        float* t = g_table + ((size_t)(s * NPAIR + kp) * 16);
        t[0  + h] = NA;
        t[2  + h] = NB2;
        t[4  + h] = ND;
        t[6  + h] = -mx;
        t[8  + h] = -my;
        t[10 + h] = mask * op;
        t[12 + h] = mask * op * ft;
        t[14 + h] = 0.0f;
    }
}

// ---------------------------------------------------------------------------
// Kernel 3: render. One thread per (pixel, slice). 2 gaussians/iter via
// packed f32x2, centered quadratic form (well-conditioned). Coefficient
// chunks staged through shared memory (broadcast LDS, conflict-free).
// ---------------------------------------------------------------------------
__global__ void __launch_bounds__(256) k_render(float* __restrict__ out) {
    // 32KB staging buffer: 512 pairs * 64B
    __shared__ __align__(16) uint4 smtab[2048];

    int gtid = blockIdx.x * 256 + threadIdx.x;
    int s = gtid >> 14;          // 16384 pixels per slice; block is slice-uniform
    int p = gtid & 16383;
    int i = p >> 7;              // row (y)
    int j = p & 127;             // col (x)

    float xx = -1.0f + (float)j * (2.0f / 127.0f);
    float yy = -1.0f + (float)i * (2.0f / 127.0f);

    uint64_t Xp = pk2(xx, xx);
    uint64_t Yp = pk2(yy, yy);

    const uint4* tab = reinterpret_cast<const uint4*>(g_table) + (size_t)s * NPAIR * 4;

    float img = 0.0f, acc = 0.0f;

#pragma unroll 1
    for (int c = 0; c < 4; c++) {
        // stage chunk c (512 pairs = 2048 uint4) into smem
        const uint4* gsrc = tab + (size_t)c * 2048;
        __syncthreads();
#pragma unroll 8
        for (int t = threadIdx.x; t < 2048; t += 256)
            smtab[t] = gsrc[t];
        __syncthreads();

        uint64_t S1 = pk2(0.0f, 0.0f);
        uint64_t S2 = pk2(0.0f, 0.0f);
        const uint64_t* sp = reinterpret_cast<const uint64_t*>(smtab);

#pragma unroll 4
        for (int kp = 0; kp < 512; kp++) {
            // 8 packed values per pair, read as 4x LDS.128
            uint64_t NA, NB2, ND, NMX, NMY, OPp, OFTp;
            {
                uint64_t v0, v1;
                asm("ld.shared.v2.u64 {%0,%1}, [%2];" : "=l"(v0), "=l"(v1)
                    : "l"(&sp[kp * 8 + 0]));
                NA = v0; NB2 = v1;
                asm("ld.shared.v2.u64 {%0,%1}, [%2];" : "=l"(v0), "=l"(v1)
                    : "l"(&sp[kp * 8 + 2]));
                ND = v0; NMX = v1;
                asm("ld.shared.v2.u64 {%0,%1}, [%2];" : "=l"(v0), "=l"(v1)
                    : "l"(&sp[kp * 8 + 4]));
                NMY = v0; OPp = v1;
                asm("ld.shared.v2.u64 {%0,%1}, [%2];" : "=l"(v0), "=l"(v1)
                    : "l"(&sp[kp * 8 + 6]));
                OFTp = v0;
            }

            uint64_t dx = add2(Xp, NMX);
            uint64_t dy = add2(Yp, NMY);
            uint64_t t0 = mul2(NB2, dy);
            t0 = fma2(NA, dx, t0);           // A*dx + 2B*dy   (pre-scaled)
            uint64_t t1 = mul2(ND, dy);
            uint64_t t2 = mul2(t1, dy);      // D*dy^2
            uint64_t q  = fma2(t0, dx, t2);  // -0.5*log2e * maha

            float ql, qh;
            upk2(q, ql, qh);
            uint64_t g = pk2(ex2a(ql), ex2a(qh));

            S2 = fma2(g, OPp, S2);
            uint64_t gg = mul2(g, g);
            S1 = fma2(gg, OFTp, S1);
        }

        float s1l, s1h, s2l, s2h;
        upk2(S1, s1l, s1h);
        upk2(S2, s2l, s2h);
        float om = 1.0f - acc;
        img = fmaf(om, s1l + s1h, img);
        acc = fmaf(om, s2l + s2h, acc);
    }

    // BACKGROUND == 0, so no final background term
    out[gtid] = img;
}

// ---------------------------------------------------------------------------
extern "C" void kernel_launch(void* const* d_in, const int* in_sizes, int n_in,
                              void* d_out, int out_size) {
    const float* means  = (const float*)d_in[0];
    const float* scales = (const float*)d_in[1];
    const float* rots   = (const float*)d_in[2];
    const float* opac   = (const float*)d_in[3];
    const float* feat   = (const float*)d_in[4];
    float* out = (float*)d_out;

    k_maxscale<<<1, 256>>>(scales);
    k_precompute<<<16, 256>>>(means, scales, rots, opac, feat);
    k_render<<<256, 256>>>(out);
}

// round 3
// speedup vs baseline: 1.2052x; 1.2052x over previous
#include <cuda_runtime.h>
#include <cstdint>

#define N_GAUSS 4096
#define NPAIR   2048
#define NSLICE  4
#define EPSF    1e-6f
// -0.5 * log2(e)
#define NHL2E  -0.72134752044448170367996234050095f

// pair-interleaved table: per slice, per gaussian-pair kp, 16 floats:
// [NA(a,b), NB2(a,b), ND(a,b), NMX(a,b), NMY(a,b), OP(a,b), OFT(a,b), pad]
// NA = NHL2E*A, NB2 = NHL2E*2B, ND = NHL2E*D (sign+scale folded in),
// NMX = -mu_x(slice), NMY = -mu_y(slice), OP = mask*op, OFT = mask*op*ft.
__device__ __align__(16) float g_table[NSLICE * NPAIR * 16];
// per-(slice,chunk,pixel) partial sums (S1, S2)
__device__ float2 g_partial[NSLICE * 4 * 16384];

// ---------------------------------------------------------------------------
// packed f32x2 helpers
// ---------------------------------------------------------------------------
__device__ __forceinline__ uint64_t pk2(float lo, float hi) {
    uint64_t r;
    asm("mov.b64 %0, {%1,%2};" : "=l"(r) : "f"(lo), "f"(hi));
    return r;
}
__device__ __forceinline__ void upk2(uint64_t v, float& lo, float& hi) {
    asm("mov.b64 {%0,%1}, %2;" : "=f"(lo), "=f"(hi) : "l"(v));
}
__device__ __forceinline__ uint64_t fma2(uint64_t a, uint64_t b, uint64_t c) {
    uint64_t d;
    asm("fma.rn.f32x2 %0, %1, %2, %3;" : "=l"(d) : "l"(a), "l"(b), "l"(c));
    return d;
}
__device__ __forceinline__ uint64_t mul2(uint64_t a, uint64_t b) {
    uint64_t d;
    asm("mul.rn.f32x2 %0, %1, %2;" : "=l"(d) : "l"(a), "l"(b));
    return d;
}
__device__ __forceinline__ uint64_t add2(uint64_t a, uint64_t b) {
    uint64_t d;
    asm("add.rn.f32x2 %0, %1, %2;" : "=l"(d) : "l"(a), "l"(b));
    return d;
}
__device__ __forceinline__ float ex2a(float x) {
    float r;
    asm("ex2.approx.f32 %0, %1;" : "=f"(r) : "f"(x));
    return r;
}

// ---------------------------------------------------------------------------
// Kernel 1: precompute with fused max reduction (every block redundantly
// computes max(scales[:,2]); 16 blocks x 256 threads, 1 gaussian/thread)
// ---------------------------------------------------------------------------
__global__ void __launch_bounds__(256) k_precompute(
        const float* __restrict__ means,
        const float* __restrict__ scales,
        const float* __restrict__ rot,
        const float* __restrict__ opac,
        const float* __restrict__ feat) {
    __shared__ float red[256];
    // block-local (redundant) max over all 4096 z-scales
    float m = 0.0f;
    for (int k = threadIdx.x; k < N_GAUSS; k += 256)
        m = fmaxf(m, scales[k * 3 + 2]);
    red[threadIdx.x] = m;
    __syncthreads();
    for (int s = 128; s > 0; s >>= 1) {
        if (threadIdx.x < s) red[threadIdx.x] = fmaxf(red[threadIdx.x], red[threadIdx.x + s]);
        __syncthreads();
    }
    float md = 3.0f * red[0];

    int k = blockIdx.x * 256 + threadIdx.x;

    float qw = rot[k * 4 + 0], qx = rot[k * 4 + 1], qy = rot[k * 4 + 2], qz = rot[k * 4 + 3];
    float inq = rsqrtf(qw * qw + qx * qx + qy * qy + qz * qz);
    float w = qw * inq, x = qx * inq, y = qy * inq, z = qz * inq;

    float r00 = 1.f - 2.f * (y * y + z * z);
    float r01 = 2.f * (x * y - w * z);
    float r02 = 2.f * (x * z + w * y);
    float r10 = 2.f * (x * y + w * z);
    float r11 = 1.f - 2.f * (x * x + z * z);
    float r12 = 2.f * (y * z - w * x);
    float r20 = 2.f * (x * z - w * y);
    float r21 = 2.f * (y * z + w * x);
    float r22 = 1.f - 2.f * (x * x + y * y);

    float sx = scales[k * 3 + 0], sy = scales[k * 3 + 1], sz = scales[k * 3 + 2];
    float m00 = r00 * sx, m01 = r01 * sy, m02 = r02 * sz;
    float m10 = r10 * sx, m11 = r11 * sy, m12 = r12 * sz;
    float m20 = r20 * sx, m21 = r21 * sy, m22 = r22 * sz;

    float c00 = m00 * m00 + m01 * m01 + m02 * m02;
    float c01 = m00 * m10 + m01 * m11 + m02 * m12;
    float c11 = m10 * m10 + m11 * m11 + m12 * m12;
    float c02 = m00 * m20 + m01 * m21 + m02 * m22;
    float c12 = m10 * m20 + m11 * m21 + m12 * m22;
    float c22 = m20 * m20 + m21 * m21 + m22 * m22;

    float szz = c22 + EPSF;
    float rx = c02 / szz;
    float ry = c12 / szz;

    float s00 = c00 - c02 * c02 / szz + EPSF;
    float s01 = c01 - c02 * c12 / szz;
    float s11 = c11 - c12 * c12 / szz + EPSF;
    float det = s00 * s11 - s01 * s01;
    float A  = s11 / det;
    float Bc = -s01 / det;
    float D  = s00 / det;

    float NA  = NHL2E * A;
    float NB2 = NHL2E * 2.0f * Bc;
    float ND  = NHL2E * D;

    float mx0 = means[k * 3 + 0], my0 = means[k * 3 + 1], mz = means[k * 3 + 2];
    float op = opac[k];
    float ft = feat[k];

    int kp = k >> 1;
    int h  = k & 1;

#pragma unroll
    for (int s = 0; s < NSLICE; s++) {
        float zs = -0.15f + 0.1f * (float)s;   // linspace(-0.15, 0.15, 4)
        float zoff = zs - mz;
        float mx = mx0 + rx * zoff;
        float my = my0 + ry * zoff;
        float mask = (fabsf(mz - zs) < md) ? 1.0f : 0.0f;

        float* t = g_table + ((size_t)(s * NPAIR + kp) * 16);
        t[0  + h] = NA;
        t[2  + h] = NB2;
        t[4  + h] = ND;
        t[6  + h] = -mx;
        t[8  + h] = -my;
        t[10 + h] = mask * op;
        t[12 + h] = mask * op * ft;
        t[14 + h] = 0.0f;
    }
}

// ---------------------------------------------------------------------------
// Kernel 2: partial render. Block = one (slice, chunk, 4-row tile).
// Thread: 2 pixels in the same row (shared dy-terms), 2 gaussians per
// iteration via packed f32x2. Writes per-chunk (S1, S2) partials.
// grid = 512 = NSLICE(4) * chunks(4) * tiles(32); block = 256.
// ---------------------------------------------------------------------------
__global__ void __launch_bounds__(256) k_render_part() {
    __shared__ __align__(16) ulonglong2 smt[2048];   // 512 pairs * 32B? no: 512*4 u128 = 32KB

    int bid  = blockIdx.x;
    int s    = bid >> 7;         // slice
    int c    = (bid >> 5) & 3;   // chunk
    int tile = bid & 31;         // 4-row tile

    // stage this chunk's 512 pairs (32KB) into smem
    const uint4* gsrc = reinterpret_cast<const uint4*>(g_table)
                        + ((size_t)s * NPAIR + (size_t)c * 512) * 4;
    uint4* sdst = reinterpret_cast<uint4*>(smt);
#pragma unroll 8
    for (int t = threadIdx.x; t < 2048; t += 256)
        sdst[t] = __ldg(gsrc + t);
    __syncthreads();

    int i = tile * 4 + (threadIdx.x >> 6);   // row
    int j = threadIdx.x & 63;                // col in [0,64); pixel pair (j, j+64)

    float yv = -1.0f + (float)i * (2.0f / 127.0f);
    float x0 = -1.0f + (float)j * (2.0f / 127.0f);
    float x1 = x0 + 64.0f * (2.0f / 127.0f);

    uint64_t Y  = pk2(yv, yv);
    uint64_t Xa = pk2(x0, x0);
    uint64_t Xb = pk2(x1, x1);

    uint64_t S1a = pk2(0.f, 0.f), S2a = S1a, S1b = S1a, S2b = S1a;

    const ulonglong2* sp = smt;
    const unsigned long long* sp64 = reinterpret_cast<const unsigned long long*>(smt);

#pragma unroll 4
    for (int kp = 0; kp < 512; kp++) {
        ulonglong2 v0 = sp[kp * 4 + 0];   // NA | NB2
        ulonglong2 v1 = sp[kp * 4 + 1];   // ND | NMX
        ulonglong2 v2 = sp[kp * 4 + 2];   // NMY | OP
        uint64_t  OFT = sp64[kp * 8 + 6]; // OFT

        uint64_t dy = add2(Y, v2.x);
        uint64_t t0 = mul2(v0.y, dy);          // 2B' * dy
        uint64_t t2 = mul2(v1.x, dy);
        t2 = mul2(t2, dy);                     // D' * dy^2

        uint64_t dxa = add2(Xa, v1.y);
        uint64_t ta  = fma2(v0.x, dxa, t0);
        uint64_t qa  = fma2(ta, dxa, t2);      // -0.5*log2e*maha (pixel a)

        uint64_t dxb = add2(Xb, v1.y);
        uint64_t tb  = fma2(v0.x, dxb, t0);
        uint64_t qb  = fma2(tb, dxb, t2);      // (pixel b)

        float l, h;
        upk2(qa, l, h);
        uint64_t ga = pk2(ex2a(l), ex2a(h));
        upk2(qb, l, h);
        uint64_t gb = pk2(ex2a(l), ex2a(h));

        S2a = fma2(ga, v2.y, S2a);
        S1a = fma2(mul2(ga, ga), OFT, S1a);
        S2b = fma2(gb, v2.y, S2b);
        S1b = fma2(mul2(gb, gb), OFT, S1b);
    }

    float s1l, s1h, s2l, s2h;
    int p0 = i * 128 + j;
    float2* dst = g_partial + (size_t)(s * 4 + c) * 16384;

    upk2(S1a, s1l, s1h);
    upk2(S2a, s2l, s2h);
    dst[p0] = make_float2(s1l + s1h, s2l + s2h);

    upk2(S1b, s1l, s1h);
    upk2(S2b, s2l, s2h);
    dst[p0 + 64] = make_float2(s1l + s1h, s2l + s2h);
}

// ---------------------------------------------------------------------------
// Kernel 3: fold chunks with transmittance recurrence (== reference scan)
// ---------------------------------------------------------------------------
__global__ void __launch_bounds__(256) k_fold(float* __restrict__ out) {
    int g = blockIdx.x * 256 + threadIdx.x;   // 65536
    int s = g >> 14;
    int p = g & 16383;
    const float2* base = g_partial + (size_t)s * 4 * 16384 + p;

    float img = 0.0f, T = 1.0f;
#pragma unroll
    for (int c = 0; c < 4; c++) {
        float2 v = base[(size_t)c * 16384];
        img = fmaf(T, v.x, img);    // img += (1-acc) * S1
        T   = T * (1.0f - v.y);     // (1-acc) *= (1 - S2)
    }
    out[g] = img;   // BACKGROUND == 0
}

// ---------------------------------------------------------------------------
extern "C" void kernel_launch(void* const* d_in, const int* in_sizes, int n_in,
                              void* d_out, int out_size) {
    const float* means  = (const float*)d_in[0];
    const float* scales = (const float*)d_in[1];
    const float* rots   = (const float*)d_in[2];
    const float* opac   = (const float*)d_in[3];
    const float* feat   = (const float*)d_in[4];
    float* out = (float*)d_out;

    k_precompute<<<16, 256>>>(means, scales, rots, opac, feat);
    k_render_part<<<512, 256>>>();
    k_fold<<<256, 256>>>(out);
}

// round 4
// speedup vs baseline: 1.6293x; 1.3519x over previous
#include <cuda_runtime.h>
#include <cstdint>

#define N_GAUSS 4096
#define NPAIR   2048
#define NSLICE  4
#define EPSF    1e-6f
// -0.5 * log2(e)
#define NHL2E  -0.72134752044448170367996234050095f

// pair-interleaved table: per slice, per gaussian-pair kp, 16 floats:
// [NA(a,b), NB2(a,b), ND(a,b), NMX(a,b), NMY(a,b), OP(a,b), OFT(a,b), pad]
// NA = NHL2E*A, NB2 = NHL2E*2B, ND = NHL2E*D (sign+scale folded in),
// NMX = -mu_x(slice), NMY = -mu_y(slice), OP = mask*op, OFT = mask*op*ft.
__device__ __align__(16) float g_table[NSLICE * NPAIR * 16];
// per-(slice, subchunk, pixel) partial sums (S1, S2); 8 subchunks of 512
__device__ float2 g_partial[NSLICE * 8 * 16384];

// ---------------------------------------------------------------------------
// packed f32x2 helpers
// ---------------------------------------------------------------------------
__device__ __forceinline__ uint64_t pk2(float lo, float hi) {
    uint64_t r;
    asm("mov.b64 %0, {%1,%2};" : "=l"(r) : "f"(lo), "f"(hi));
    return r;
}
__device__ __forceinline__ void upk2(uint64_t v, float& lo, float& hi) {
    asm("mov.b64 {%0,%1}, %2;" : "=f"(lo), "=f"(hi) : "l"(v));
}
__device__ __forceinline__ uint64_t fma2(uint64_t a, uint64_t b, uint64_t c) {
    uint64_t d;
    asm("fma.rn.f32x2 %0, %1, %2, %3;" : "=l"(d) : "l"(a), "l"(b), "l"(c));
    return d;
}
__device__ __forceinline__ uint64_t mul2(uint64_t a, uint64_t b) {
    uint64_t d;
    asm("mul.rn.f32x2 %0, %1, %2;" : "=l"(d) : "l"(a), "l"(b));
    return d;
}
__device__ __forceinline__ uint64_t add2(uint64_t a, uint64_t b) {
    uint64_t d;
    asm("add.rn.f32x2 %0, %1, %2;" : "=l"(d) : "l"(a), "l"(b));
    return d;
}
__device__ __forceinline__ float ex2a(float x) {
    float r;
    asm("ex2.approx.f32 %0, %1;" : "=f"(r) : "f"(x));
    return r;
}

// ---------------------------------------------------------------------------
// Kernel 1: precompute with fused (redundant per-block) max reduction.
// 32 blocks x 128 threads, 1 gaussian/thread.
// ---------------------------------------------------------------------------
__global__ void __launch_bounds__(128) k_precompute(
        const float* __restrict__ means,
        const float* __restrict__ scales,
        const float* __restrict__ rot,
        const float* __restrict__ opac,
        const float* __restrict__ feat) {
    __shared__ float red[4];
    int lid = threadIdx.x & 31;
    int wid = threadIdx.x >> 5;

    // block-local max over all 4096 z-scales
    float m = 0.0f;
    for (int k = threadIdx.x; k < N_GAUSS; k += 128)
        m = fmaxf(m, __ldg(&scales[k * 3 + 2]));
#pragma unroll
    for (int o = 16; o > 0; o >>= 1)
        m = fmaxf(m, __shfl_xor_sync(0xffffffffu, m, o));
    if (lid == 0) red[wid] = m;
    __syncthreads();
    float md = 3.0f * fmaxf(fmaxf(red[0], red[1]), fmaxf(red[2], red[3]));

    int k = blockIdx.x * 128 + threadIdx.x;

    float qw = rot[k * 4 + 0], qx = rot[k * 4 + 1], qy = rot[k * 4 + 2], qz = rot[k * 4 + 3];
    float inq = rsqrtf(qw * qw + qx * qx + qy * qy + qz * qz);
    float w = qw * inq, x = qx * inq, y = qy * inq, z = qz * inq;

    float r00 = 1.f - 2.f * (y * y + z * z);
    float r01 = 2.f * (x * y - w * z);
    float r02 = 2.f * (x * z + w * y);
    float r10 = 2.f * (x * y + w * z);
    float r11 = 1.f - 2.f * (x * x + z * z);
    float r12 = 2.f * (y * z - w * x);
    float r20 = 2.f * (x * z - w * y);
    float r21 = 2.f * (y * z + w * x);
    float r22 = 1.f - 2.f * (x * x + y * y);

    float sx = scales[k * 3 + 0], sy = scales[k * 3 + 1], sz = scales[k * 3 + 2];
    float m00 = r00 * sx, m01 = r01 * sy, m02 = r02 * sz;
    float m10 = r10 * sx, m11 = r11 * sy, m12 = r12 * sz;
    float m20 = r20 * sx, m21 = r21 * sy, m22 = r22 * sz;

    float c00 = m00 * m00 + m01 * m01 + m02 * m02;
    float c01 = m00 * m10 + m01 * m11 + m02 * m12;
    float c11 = m10 * m10 + m11 * m11 + m12 * m12;
    float c02 = m00 * m20 + m01 * m21 + m02 * m22;
    float c12 = m10 * m20 + m11 * m21 + m12 * m22;
    float c22 = m20 * m20 + m21 * m21 + m22 * m22;

    float szz = c22 + EPSF;
    float rx = c02 / szz;
    float ry = c12 / szz;

    float s00 = c00 - c02 * c02 / szz + EPSF;
    float s01 = c01 - c02 * c12 / szz;
    float s11 = c11 - c12 * c12 / szz + EPSF;
    float det = s00 * s11 - s01 * s01;
    float A  = s11 / det;
    float Bc = -s01 / det;
    float D  = s00 / det;

    float NA  = NHL2E * A;
    float NB2 = NHL2E * 2.0f * Bc;
    float ND  = NHL2E * D;

    float mx0 = means[k * 3 + 0], my0 = means[k * 3 + 1], mz = means[k * 3 + 2];
    float op = opac[k];
    float ft = feat[k];

    int kp = k >> 1;
    int h  = k & 1;

#pragma unroll
    for (int s = 0; s < NSLICE; s++) {
        float zs = -0.15f + 0.1f * (float)s;   // linspace(-0.15, 0.15, 4)
        float zoff = zs - mz;
        float mx = mx0 + rx * zoff;
        float my = my0 + ry * zoff;
        float mask = (fabsf(mz - zs) < md) ? 1.0f : 0.0f;

        float* t = g_table + ((size_t)(s * NPAIR + kp) * 16);
        t[0  + h] = NA;
        t[2  + h] = NB2;
        t[4  + h] = ND;
        t[6  + h] = -mx;
        t[8  + h] = -my;
        t[10 + h] = mask * op;
        t[12 + h] = mask * op * ft;
        t[14 + h] = 0.0f;
    }
}

// ---------------------------------------------------------------------------
// Kernel 2: partial render.
// Block = one (slice, subchunk of 512 gaussians, 4-row tile).
// Thread: 4 pixels in one row (cols j, j+32, j+64, j+96) -> dy-terms shared;
// 2 gaussians per iteration via packed f32x2.
// grid = 1024 = 4 slices * 8 subchunks * 32 tiles; block = 128.
// ---------------------------------------------------------------------------
__global__ void __launch_bounds__(128, 8) k_render_part() {
    __shared__ __align__(16) uint4 smt[1024];   // 256 pairs * 64B = 16KB

    int bid  = blockIdx.x;
    int s    = bid >> 8;         // slice
    int sub  = (bid >> 5) & 7;   // subchunk (512 gaussians = 256 pairs)
    int tile = bid & 31;         // 4-row tile

    // stage this subchunk's 256 pairs (16KB) into smem
    const uint4* gsrc = reinterpret_cast<const uint4*>(g_table)
                        + ((size_t)s * NPAIR + (size_t)sub * 256) * 4;
#pragma unroll 8
    for (int t = threadIdx.x; t < 1024; t += 128)
        smt[t] = __ldg(gsrc + t);
    __syncthreads();

    int i = tile * 4 + (threadIdx.x >> 5);   // row
    int j = threadIdx.x & 31;                // base col; pixels j+32p

    float yv = -1.0f + (float)i * (2.0f / 127.0f);
    float x0 = -1.0f + (float)j * (2.0f / 127.0f);

    uint64_t Y = pk2(yv, yv);
    uint64_t X[4];
#pragma unroll
    for (int p = 0; p < 4; p++) {
        float xv = x0 + (float)(32 * p) * (2.0f / 127.0f);
        X[p] = pk2(xv, xv);
    }

    uint64_t S1[4], S2[4];
#pragma unroll
    for (int p = 0; p < 4; p++) { S1[p] = pk2(0.f, 0.f); S2[p] = pk2(0.f, 0.f); }

    const ulonglong2* sp   = reinterpret_cast<const ulonglong2*>(smt);
    const unsigned long long* sp64 = reinterpret_cast<const unsigned long long*>(smt);

#pragma unroll 4
    for (int kp = 0; kp < 256; kp++) {
        ulonglong2 v0 = sp[kp * 4 + 0];   // NA | NB2
        ulonglong2 v1 = sp[kp * 4 + 1];   // ND | NMX
        ulonglong2 v2 = sp[kp * 4 + 2];   // NMY | OP
        uint64_t  OFT = sp64[kp * 8 + 6]; // OFT

        uint64_t dy = add2(Y, v2.x);
        uint64_t t0 = mul2(v0.y, dy);          // 2B' * dy
        uint64_t t2 = mul2(mul2(v1.x, dy), dy);// D' * dy^2

#pragma unroll
        for (int p = 0; p < 4; p++) {
            uint64_t dx = add2(X[p], v1.y);
            uint64_t q  = fma2(fma2(v0.x, dx, t0), dx, t2);  // -0.5*log2e*maha
            float l, h;
            upk2(q, l, h);
            uint64_t g = pk2(ex2a(l), ex2a(h));
            S2[p] = fma2(g, v2.y, S2[p]);
            S1[p] = fma2(mul2(g, g), OFT, S1[p]);
        }
    }

    int p0 = i * 128 + j;
    float2* dst = g_partial + (size_t)(s * 8 + sub) * 16384;
#pragma unroll
    for (int p = 0; p < 4; p++) {
        float s1l, s1h, s2l, s2h;
        upk2(S1[p], s1l, s1h);
        upk2(S2[p], s2l, s2h);
        dst[p0 + 32 * p] = make_float2(s1l + s1h, s2l + s2h);
    }
}

// ---------------------------------------------------------------------------
// Kernel 3: fold subchunks: pair-add to chunk sums, then transmittance
// recurrence over the 4 chunks (== reference scan).
// ---------------------------------------------------------------------------
__global__ void __launch_bounds__(256) k_fold(float* __restrict__ out) {
    int g = blockIdx.x * 256 + threadIdx.x;   // 65536
    int s = g >> 14;
    int p = g & 16383;
    const float2* base = g_partial + (size_t)s * 8 * 16384 + p;

    float img = 0.0f, T = 1.0f;
#pragma unroll
    for (int c = 0; c < 4; c++) {
        float2 va = base[(size_t)(2 * c)     * 16384];
        float2 vb = base[(size_t)(2 * c + 1) * 16384];
        float S1 = va.x + vb.x;
        float S2 = va.y + vb.y;
        img = fmaf(T, S1, img);    // img += (1-acc) * S1
        T   = T * (1.0f - S2);     // (1-acc) *= (1 - S2)
    }
    out[g] = img;   // BACKGROUND == 0
}

// ---------------------------------------------------------------------------
extern "C" void kernel_launch(void* const* d_in, const int* in_sizes, int n_in,
                              void* d_out, int out_size) {
    const float* means  = (const float*)d_in[0];
    const float* scales = (const float*)d_in[1];
    const float* rots   = (const float*)d_in[2];
    const float* opac   = (const float*)d_in[3];
    const float* feat   = (const float*)d_in[4];
    float* out = (float*)d_out;

    k_precompute<<<32, 128>>>(means, scales, rots, opac, feat);
    k_render_part<<<1024, 128>>>();
    k_fold<<<256, 256>>>(out);
}

// round 5
// speedup vs baseline: 1.6589x; 1.0182x over previous
#include <cuda_runtime.h>
#include <cstdint>

#define N_GAUSS 4096
#define NPAIR   2048
#define NSLICE  4
#define EPSF    1e-6f
// -0.5 * log2(e)
#define NHL2E  -0.72134752044448170367996234050095f
// pixel x stride for W=8 (16 columns apart)
#define HSTEP   (16.0f * (2.0f / 127.0f))

// pair-interleaved table: per slice, per gaussian-pair kp, 16 floats:
// [NA(a,b), NB2(a,b), ND(a,b), NMX(a,b), NMY(a,b), OP(a,b), OFT(a,b), pad]
__device__ __align__(16) float g_table[NSLICE * NPAIR * 16];
// per-(slice, subchunk, pixel) partial sums (S1, S2); 16 subchunks of 256
__device__ float2 g_partial[NSLICE * 16 * 16384];

// ---------------------------------------------------------------------------
// packed f32x2 helpers
// ---------------------------------------------------------------------------
__device__ __forceinline__ uint64_t pk2(float lo, float hi) {
    uint64_t r;
    asm("mov.b64 %0, {%1,%2};" : "=l"(r) : "f"(lo), "f"(hi));
    return r;
}
__device__ __forceinline__ void upk2(uint64_t v, float& lo, float& hi) {
    asm("mov.b64 {%0,%1}, %2;" : "=f"(lo), "=f"(hi) : "l"(v));
}
__device__ __forceinline__ uint64_t fma2(uint64_t a, uint64_t b, uint64_t c) {
    uint64_t d;
    asm("fma.rn.f32x2 %0, %1, %2, %3;" : "=l"(d) : "l"(a), "l"(b), "l"(c));
    return d;
}
__device__ __forceinline__ uint64_t mul2(uint64_t a, uint64_t b) {
    uint64_t d;
    asm("mul.rn.f32x2 %0, %1, %2;" : "=l"(d) : "l"(a), "l"(b));
    return d;
}
__device__ __forceinline__ uint64_t add2(uint64_t a, uint64_t b) {
    uint64_t d;
    asm("add.rn.f32x2 %0, %1, %2;" : "=l"(d) : "l"(a), "l"(b));
    return d;
}
__device__ __forceinline__ float ex2a(float x) {
    float r;
    asm("ex2.approx.f32 %0, %1;" : "=f"(r) : "f"(x));
    return r;
}

// ---------------------------------------------------------------------------
// Kernel 1: precompute. One thread per (gaussian, slice): 16384 threads.
// Each block redundantly computes max(scales[:,2]).
// ---------------------------------------------------------------------------
__global__ void __launch_bounds__(128) k_precompute(
        const float* __restrict__ means,
        const float* __restrict__ scales,
        const float* __restrict__ rot,
        const float* __restrict__ opac,
        const float* __restrict__ feat) {
    __shared__ float red[4];
    int lid = threadIdx.x & 31;
    int wid = threadIdx.x >> 5;

    // block-local max over all 4096 z-scales
    float m = 0.0f;
    for (int k = threadIdx.x; k < N_GAUSS; k += 128)
        m = fmaxf(m, __ldg(&scales[k * 3 + 2]));
#pragma unroll
    for (int o = 16; o > 0; o >>= 1)
        m = fmaxf(m, __shfl_xor_sync(0xffffffffu, m, o));
    if (lid == 0) red[wid] = m;
    __syncthreads();
    float md = 3.0f * fmaxf(fmaxf(red[0], red[1]), fmaxf(red[2], red[3]));

    int g = blockIdx.x * 128 + threadIdx.x;   // 16384
    int k = g & (N_GAUSS - 1);
    int s = g >> 12;

    float qw = rot[k * 4 + 0], qx = rot[k * 4 + 1], qy = rot[k * 4 + 2], qz = rot[k * 4 + 3];
    float inq = rsqrtf(qw * qw + qx * qx + qy * qy + qz * qz);
    float w = qw * inq, x = qx * inq, y = qy * inq, z = qz * inq;

    float r00 = 1.f - 2.f * (y * y + z * z);
    float r01 = 2.f * (x * y - w * z);
    float r02 = 2.f * (x * z + w * y);
    float r10 = 2.f * (x * y + w * z);
    float r11 = 1.f - 2.f * (x * x + z * z);
    float r12 = 2.f * (y * z - w * x);
    float r20 = 2.f * (x * z - w * y);
    float r21 = 2.f * (y * z + w * x);
    float r22 = 1.f - 2.f * (x * x + y * y);

    float sx = scales[k * 3 + 0], sy = scales[k * 3 + 1], sz = scales[k * 3 + 2];
    float m00 = r00 * sx, m01 = r01 * sy, m02 = r02 * sz;
    float m10 = r10 * sx, m11 = r11 * sy, m12 = r12 * sz;
    float m20 = r20 * sx, m21 = r21 * sy, m22 = r22 * sz;

    float c00 = m00 * m00 + m01 * m01 + m02 * m02;
    float c01 = m00 * m10 + m01 * m11 + m02 * m12;
    float c11 = m10 * m10 + m11 * m11 + m12 * m12;
    float c02 = m00 * m20 + m01 * m21 + m02 * m22;
    float c12 = m10 * m20 + m11 * m21 + m12 * m22;
    float c22 = m20 * m20 + m21 * m21 + m22 * m22;

    float szz = c22 + EPSF;
    float rx = c02 / szz;
    float ry = c12 / szz;

    float s00 = c00 - c02 * c02 / szz + EPSF;
    float s01 = c01 - c02 * c12 / szz;
    float s11 = c11 - c12 * c12 / szz + EPSF;
    float det = s00 * s11 - s01 * s01;
    float A  = s11 / det;
    float Bc = -s01 / det;
    float D  = s00 / det;

    float mx0 = means[k * 3 + 0], my0 = means[k * 3 + 1], mz = means[k * 3 + 2];
    float op = opac[k];
    float ft = feat[k];

    float zs = -0.15f + 0.1f * (float)s;   // linspace(-0.15, 0.15, 4)
    float zoff = zs - mz;
    float mx = mx0 + rx * zoff;
    float my = my0 + ry * zoff;
    float mask = (fabsf(mz - zs) < md) ? 1.0f : 0.0f;

    int kp = k >> 1;
    int h  = k & 1;
    float* t = g_table + ((size_t)(s * NPAIR + kp) * 16);
    t[0  + h] = NHL2E * A;
    t[2  + h] = NHL2E * 2.0f * Bc;
    t[4  + h] = NHL2E * D;
    t[6  + h] = -mx;
    t[8  + h] = -my;
    t[10 + h] = mask * op;
    t[12 + h] = mask * op * ft;
    t[14 + h] = 0.0f;
}

// ---------------------------------------------------------------------------
// Kernel 2: partial render.
// Block = one (slice, subchunk of 256 gaussians, 8-row tile). 128 threads.
// Thread: 8 pixels in one row (cols j + 16p), incremental dx; 2 gaussians
// per iteration via packed f32x2.
// grid = 1024 = 4 slices * 16 subchunks * 16 tiles.
// ---------------------------------------------------------------------------
__global__ void __launch_bounds__(128, 7) k_render_part() {
    __shared__ __align__(16) uint4 smt[512];   // 128 pairs * 64B = 8KB

    int bid  = blockIdx.x;
    int s    = bid >> 8;         // slice
    int sub  = (bid >> 4) & 15;  // subchunk (256 gaussians = 128 pairs)
    int tile = bid & 15;         // 8-row tile

    // stage this subchunk's 128 pairs (8KB) into smem
    const uint4* gsrc = reinterpret_cast<const uint4*>(g_table)
                        + ((size_t)s * NPAIR + (size_t)sub * 128) * 4;
#pragma unroll 4
    for (int t = threadIdx.x; t < 512; t += 128)
        smt[t] = __ldg(gsrc + t);
    __syncthreads();

    int i = tile * 8 + (threadIdx.x >> 4);   // row
    int j = threadIdx.x & 15;                // base col; pixels j + 16p

    float yv = -1.0f + (float)i * (2.0f / 127.0f);
    float x0 = -1.0f + (float)j * (2.0f / 127.0f);

    uint64_t Y  = pk2(yv, yv);
    uint64_t X0 = pk2(x0, x0);
    uint64_t Hc = pk2(HSTEP, HSTEP);

    uint64_t S1[8], S2[8];
#pragma unroll
    for (int p = 0; p < 8; p++) { S1[p] = pk2(0.f, 0.f); S2[p] = pk2(0.f, 0.f); }

    const ulonglong2* sp = reinterpret_cast<const ulonglong2*>(smt);
    const unsigned long long* sp64 = reinterpret_cast<const unsigned long long*>(smt);

#pragma unroll 2
    for (int kp = 0; kp < 128; kp++) {
        ulonglong2 v0 = sp[kp * 4 + 0];   // NA | NB2
        ulonglong2 v1 = sp[kp * 4 + 1];   // ND | NMX
        ulonglong2 v2 = sp[kp * 4 + 2];   // NMY | OP
        uint64_t  OFT = sp64[kp * 8 + 6]; // OFT

        uint64_t dy = add2(Y, v2.x);
        uint64_t t0 = mul2(v0.y, dy);            // 2B' * dy
        uint64_t t2 = mul2(mul2(v1.x, dy), dy);  // D' * dy^2

        uint64_t dx = add2(X0, v1.y);
#pragma unroll
        for (int p = 0; p < 8; p++) {
            uint64_t q = fma2(fma2(v0.x, dx, t0), dx, t2);  // -0.5*log2e*maha
            float l, h;
            upk2(q, l, h);
            uint64_t g = pk2(ex2a(l), ex2a(h));
            S2[p] = fma2(g, v2.y, S2[p]);
            S1[p] = fma2(mul2(g, g), OFT, S1[p]);
            dx = add2(dx, Hc);
        }
    }

    int p0 = i * 128 + j;
    float2* dst = g_partial + (size_t)(s * 16 + sub) * 16384;
#pragma unroll
    for (int p = 0; p < 8; p++) {
        float s1l, s1h, s2l, s2h;
        upk2(S1[p], s1l, s1h);
        upk2(S2[p], s2l, s2h);
        dst[p0 + 16 * p] = make_float2(s1l + s1h, s2l + s2h);
    }
}

// ---------------------------------------------------------------------------
// Kernel 3: fold subchunks (4 per reference chunk), then transmittance
// recurrence over the 4 chunks (== reference scan).
// ---------------------------------------------------------------------------
__global__ void __launch_bounds__(256) k_fold(float* __restrict__ out) {
    int g = blockIdx.x * 256 + threadIdx.x;   // 65536
    int s = g >> 14;
    int p = g & 16383;
    const float2* base = g_partial + (size_t)s * 16 * 16384 + p;

    float img = 0.0f, T = 1.0f;
#pragma unroll
    for (int c = 0; c < 4; c++) {
        float S1 = 0.0f, S2 = 0.0f;
#pragma unroll
        for (int u = 0; u < 4; u++) {
            float2 v = base[(size_t)(c * 4 + u) * 16384];
            S1 += v.x;
            S2 += v.y;
        }
        img = fmaf(T, S1, img);    // img += (1-acc) * S1
        T   = T * (1.0f - S2);     // (1-acc) *= (1 - S2)
    }
    out[g] = img;   // BACKGROUND == 0
}

// ---------------------------------------------------------------------------
extern "C" void kernel_launch(void* const* d_in, const int* in_sizes, int n_in,
                              void* d_out, int out_size) {
    const float* means  = (const float*)d_in[0];
    const float* scales = (const float*)d_in[1];
    const float* rots   = (const float*)d_in[2];
    const float* opac   = (const float*)d_in[3];
    const float* feat   = (const float*)d_in[4];
    float* out = (float*)d_out;

    k_precompute<<<128, 128>>>(means, scales, rots, opac, feat);
    k_render_part<<<1024, 128>>>();
    k_fold<<<256, 256>>>(out);
}